// round 10
// baseline (speedup 1.0000x reference)
#include <cuda_runtime.h>

// CostVolume: left,right [B,C,H,W] f32 -> out [B,2C,D,H,W] f32
//   out[b, c,      d, h, w] = (w+d < W) ? left [b,c,h,w+d] : 0
//   out[b, C + c,  d, h, w] = (w-d >= 0)? right[b,c,h,w-d] : 0
//
// Fixed shapes: B=2, C=32, H=128, W=256, D=32.
//
// R10: syncless variant of the converged design. Each thread's 20-float
// window starts at a 16B-aligned offset and every float4 of it is either
// fully in-bounds or fully out-of-bounds (W % 4 == 0), so the window is
// loaded directly from global with 5 predicated LDG.128 (zero-fill OOB) —
// no smem staging, no STS, no __syncthreads. Rows are L1-resident after
// first touch (40x intra-row reuse). Store path unchanged from the best
// kernel: one uninterrupted burst of 16 x STG.128 st.global.cs per thread.
// 512-thread CTA covers 2 h-rows (grid 4096).

namespace {
constexpr int B = 2;
constexpr int C = 32;
constexpr int H = 128;
constexpr int W = 256;
constexpr int D = 32;
}

__device__ __forceinline__ void stcs128(float* p, float4 v) {
    __stcs(reinterpret_cast<float4*>(p), v);
}

__global__ __launch_bounds__(512)
void cost_volume_kernel(const float* __restrict__ left,
                        const float* __restrict__ right,
                        float* __restrict__ out) {
    const int blk = blockIdx.x;            // b*C*(H/2) + c*(H/2) + hp
    const int hp = blk & (H / 2 - 1);      // 64 row pairs per (b,c)
    const int c  = (blk >> 6) & (C - 1);
    const int b  = blk >> 11;

    const int tid   = threadIdx.x;         // 0..511
    const int rsub  = tid >> 8;            // row within pair
    const int t256  = tid & 255;
    const int half  = t256 >> 7;           // 0 = left, 1 = right
    const int dhalf = (t256 >> 6) & 1;     // d block
    const int l64   = t256 & 63;           // float4 column
    const int w4    = l64 << 2;
    const int d0    = dhalf << 4;          // 0 or 16
    const int h     = hp * 2 + rsub;

    const size_t in_off = ((((size_t)b * C + c) * H) + h) * W;
    const float* row = (half ? right : left) + in_off;

    // ---- 20-float register window: 5 predicated LDG.128 ----
    // Left  thread: f[k] = left_row [w4 + d0 + k],      k = 0..19
    // Right thread: f[k] = right_row[w4 - d0 - 16 + k], k = 0..19
    // Window float4 i sits at float offset woff + 4i; since woff is a
    // multiple of 4 and W % 4 == 0, each float4 is fully in or fully out.
    const int woff = half ? (w4 - d0 - 16) : (w4 + d0);

    float f[20];
    #pragma unroll
    for (int i = 0; i < 5; i++) {
        const int o = woff + 4 * i;
        float4 q;
        if (o >= 0 && o < W) {
            q = __ldg(reinterpret_cast<const float4*>(row + o));
        } else {
            q = make_float4(0.f, 0.f, 0.f, 0.f);
        }
        f[4 * i + 0] = q.x;
        f[4 * i + 1] = q.y;
        f[4 * i + 2] = q.z;
        f[4 * i + 3] = q.w;
    }

    // ---- emit 16 disparity planes (one uninterrupted streaming burst) ----
    const size_t dstride = (size_t)H * W;  // 32768 floats per d-plane
    float* dst = out
        + ((size_t)(b * 2 * C + half * C + c) * D + d0) * dstride
        + (size_t)h * W + w4;

    if (half == 0) {
        // d = d0 + dd: out = left_row[w4+d .. w4+d+3] = f[dd .. dd+3]
        #pragma unroll
        for (int dd = 0; dd < 16; dd++) {
            float4 v = make_float4(f[dd], f[dd + 1], f[dd + 2], f[dd + 3]);
            stcs128(dst + (size_t)dd * dstride, v);
        }
    } else {
        // d = d0 + dd: out = right_row[w4-d .. w4-d+3] = f[16-dd .. 19-dd]
        #pragma unroll
        for (int dd = 0; dd < 16; dd++) {
            float4 v = make_float4(f[16 - dd], f[17 - dd], f[18 - dd], f[19 - dd]);
            stcs128(dst + (size_t)dd * dstride, v);
        }
    }
}

extern "C" void kernel_launch(void* const* d_in, const int* in_sizes, int n_in,
                              void* d_out, int out_size) {
    const float* left  = (const float*)d_in[0];
    const float* right = (const float*)d_in[1];
    float* out = (float*)d_out;

    (void)in_sizes; (void)n_in; (void)out_size;

    const int grid = B * C * (H / 2);  // 4096 CTAs
    cost_volume_kernel<<<grid, 512>>>(left, right, out);
}